// round 1
// baseline (speedup 1.0000x reference)
#include <cuda_runtime.h>
#include <cstdint>

#define NTOK 4096
#define DIM  1024
#define NEXP 8
#define HID  4096
#define THR  0.3f

#define BM 128
#define BN 128
#define BK 32
#define PADM 136
#define PADN 136

// ---------------- scratch (static device memory; no allocs anywhere) ----------------
__device__ float g_c[NTOK * NEXP];                 // combine weights per (token, expert)
__device__ int   g_idx[NEXP][NTOK];                // compacted token indices per expert
__device__ float g_wt[NEXP][NTOK];                 // compacted combine weights
__device__ int   g_cnt[NEXP];                      // tokens per expert
__device__ float g_h[(size_t)NEXP * NTOK * HID];   // GELU hidden activations (512 MB)

// ---------------- helpers ----------------
__device__ __forceinline__ uint32_t f2tf(float f) {
    uint32_t u;
    asm("cvt.rna.tf32.f32 %0, %1;" : "=r"(u) : "f"(f));
    return u;
}

__device__ __forceinline__ void mma8(float* c, const uint32_t* a, const uint32_t* b) {
    asm volatile(
        "mma.sync.aligned.m16n8k8.row.col.f32.tf32.tf32.f32 "
        "{%0,%1,%2,%3}, {%4,%5,%6,%7}, {%8,%9}, {%0,%1,%2,%3};"
        : "+f"(c[0]), "+f"(c[1]), "+f"(c[2]), "+f"(c[3])
        : "r"(a[0]), "r"(a[1]), "r"(a[2]), "r"(a[3]), "r"(b[0]), "r"(b[1]));
}

__device__ __forceinline__ float gelu_exact(float v) {
    return 0.5f * v * (1.0f + erff(v * 0.70710678118654752f));
}

// ---------------- kernel 1: gate scores, combine weights, out init with sum(c*b2) ----------------
__global__ __launch_bounds__(256) void gate_kernel(
    const float* __restrict__ x, const float* __restrict__ wg,
    const float* __restrict__ bg, const float* __restrict__ b2,
    float* __restrict__ out)
{
    __shared__ float wgs[DIM * 9];   // padded stride 9 -> conflict-free
    int tid = threadIdx.x;
    for (int i = tid; i < DIM * NEXP; i += 256)
        wgs[(i >> 3) * 9 + (i & 7)] = wg[i];
    __syncthreads();

    int lane = tid & 31, wid = tid >> 5;
    int n = blockIdx.x * 8 + wid;

    float s[NEXP];
#pragma unroll
    for (int e = 0; e < NEXP; e++) s[e] = 0.f;

    const float* xr = x + (size_t)n * DIM;
    for (int k = lane; k < DIM; k += 32) {
        float xv = xr[k];
#pragma unroll
        for (int e = 0; e < NEXP; e++) s[e] += xv * wgs[k * 9 + e];
    }
#pragma unroll
    for (int e = 0; e < NEXP; e++)
#pragma unroll
        for (int o = 16; o; o >>= 1)
            s[e] += __shfl_xor_sync(0xffffffffu, s[e], o);

    // softmax (replicated on all lanes)
    float mx = -1e30f;
#pragma unroll
    for (int e = 0; e < NEXP; e++) { s[e] += bg[e]; mx = fmaxf(mx, s[e]); }
    float sum = 0.f;
#pragma unroll
    for (int e = 0; e < NEXP; e++) { s[e] = expf(s[e] - mx); sum += s[e]; }
    float inv = 1.f / sum;
#pragma unroll
    for (int e = 0; e < NEXP; e++) s[e] *= inv;

    if (lane == 0) {
        float* gs = out + (size_t)NTOK * DIM + (size_t)n * NEXP;
#pragma unroll
        for (int e = 0; e < NEXP; e++) gs[e] = s[e];
    }

    // combine weights: thresholded renorm, or fallback top-1
    float msum = 0.f; int cnt = 0;
#pragma unroll
    for (int e = 0; e < NEXP; e++) if (s[e] >= THR) { msum += s[e]; cnt++; }
    int top1 = 0; float best = s[0];
#pragma unroll
    for (int e = 1; e < NEXP; e++) if (s[e] > best) { best = s[e]; top1 = e; }
    float dn = 1.f / (msum + 1e-6f);
    float c[NEXP];
#pragma unroll
    for (int e = 0; e < NEXP; e++)
        c[e] = cnt ? ((s[e] >= THR) ? s[e] * dn : 0.f) : ((e == top1) ? 1.f : 0.f);

    if (lane == 0) {
#pragma unroll
        for (int e = 0; e < NEXP; e++) g_c[n * NEXP + e] = c[e];
    }

    // initialize out with sum_e c[e] * b2[e,:]
    for (int d = lane; d < DIM; d += 32) {
        float a = 0.f;
#pragma unroll
        for (int e = 0; e < NEXP; e++) a += c[e] * b2[e * DIM + d];
        out[(size_t)n * DIM + d] = a;
    }
}

// ---------------- kernel 2: deterministic per-expert compaction (1 warp per expert) ----------------
__global__ __launch_bounds__(256) void compact_kernel()
{
    int wid = threadIdx.x >> 5;
    int lane = threadIdx.x & 31;
    if (wid >= NEXP) return;
    int cnt = 0;
    for (int base = 0; base < NTOK; base += 32) {
        int n = base + lane;
        float c = g_c[n * NEXP + wid];
        unsigned m = __ballot_sync(0xffffffffu, c > 0.f);
        if (c > 0.f) {
            int pos = cnt + __popc(m & ((1u << lane) - 1u));
            g_idx[wid][pos] = n;
            g_wt[wid][pos]  = c;
        }
        cnt += __popc(m);
    }
    if (lane == 0) g_cnt[wid] = cnt;
}

// ---------------- kernel 3: grouped GEMM1: h = gelu(gather(ei) @ w1 + b1) ----------------
__global__ __launch_bounds__(256) void ffn1_kernel(
    const float* __restrict__ ei, const float* __restrict__ w1,
    const float* __restrict__ b1)
{
    const int e  = blockIdx.z;
    const int me = g_cnt[e];
    const int mt = blockIdx.x;
    if (mt * BM >= me) return;
    const int n0 = blockIdx.y * BN;

    __shared__ float As[BK][PADM];
    __shared__ float Bs[BK][PADN];

    const int tid  = threadIdx.x;
    const int lane = tid & 31;
    const int wid  = tid >> 5;
    const int wm   = wid >> 1;     // 0..3 (M groups of 32)
    const int wn   = wid & 1;      // 0..1 (N groups of 64)
    const int g    = lane >> 2;
    const int t    = lane & 3;

    // A gather loader: 4 rows per thread, 4 consecutive k each
    const int rA = tid >> 3;            // 0..31
    const int cA = (tid & 7) << 2;      // 0..28
    const float* aptr[4];
    bool aval[4];
#pragma unroll
    for (int i = 0; i < 4; i++) {
        int s = mt * BM + rA + 32 * i;
        aval[i] = (s < me);
        int tok = aval[i] ? g_idx[e][s] : 0;
        aptr[i] = ei + ((size_t)e * NTOK + tok) * DIM + cA;
    }
    // B loader: thread covers k = kB + 8i, 4 consecutive cols
    const int kB = tid >> 5;            // 0..7
    const int cB = lane << 2;           // 0..124
    const float* bbase = w1 + (size_t)e * DIM * HID + n0 + cB;

    float4 pa[4], pb[4];
#pragma unroll
    for (int i = 0; i < 4; i++)
        pa[i] = aval[i] ? *(const float4*)(aptr[i]) : make_float4(0, 0, 0, 0);
#pragma unroll
    for (int i = 0; i < 4; i++)
        pb[i] = *(const float4*)(bbase + (size_t)(kB + 8 * i) * HID);

    float acc[2][8][4];
#pragma unroll
    for (int a = 0; a < 2; a++)
#pragma unroll
        for (int b = 0; b < 8; b++)
#pragma unroll
            for (int q = 0; q < 4; q++) acc[a][b][q] = 0.f;

    const int KT = DIM / BK;
    for (int kt = 0; kt < KT; kt++) {
        __syncthreads();
#pragma unroll
        for (int i = 0; i < 4; i++) {
            int r = rA + 32 * i;
            As[cA + 0][r] = __uint_as_float(f2tf(pa[i].x));
            As[cA + 1][r] = __uint_as_float(f2tf(pa[i].y));
            As[cA + 2][r] = __uint_as_float(f2tf(pa[i].z));
            As[cA + 3][r] = __uint_as_float(f2tf(pa[i].w));
            int kk = kB + 8 * i;
            Bs[kk][cB + 0] = __uint_as_float(f2tf(pb[i].x));
            Bs[kk][cB + 1] = __uint_as_float(f2tf(pb[i].y));
            Bs[kk][cB + 2] = __uint_as_float(f2tf(pb[i].z));
            Bs[kk][cB + 3] = __uint_as_float(f2tf(pb[i].w));
        }
        __syncthreads();
        if (kt + 1 < KT) {
            int ko = (kt + 1) * BK;
#pragma unroll
            for (int i = 0; i < 4; i++)
                pa[i] = aval[i] ? *(const float4*)(aptr[i] + ko) : make_float4(0, 0, 0, 0);
#pragma unroll
            for (int i = 0; i < 4; i++)
                pb[i] = *(const float4*)(bbase + (size_t)(ko + kB + 8 * i) * HID);
        }
#pragma unroll
        for (int ks = 0; ks < 4; ks++) {
            const int k0 = ks * 8;
            uint32_t af[2][4];
#pragma unroll
            for (int mi = 0; mi < 2; mi++) {
                int m = wm * 32 + mi * 16;
                af[mi][0] = __float_as_uint(As[k0 + t][m + g]);
                af[mi][1] = __float_as_uint(As[k0 + t][m + g + 8]);
                af[mi][2] = __float_as_uint(As[k0 + t + 4][m + g]);
                af[mi][3] = __float_as_uint(As[k0 + t + 4][m + g + 8]);
            }
            uint32_t bf[8][2];
#pragma unroll
            for (int ni = 0; ni < 8; ni++) {
                int n = wn * 64 + ni * 8;
                bf[ni][0] = __float_as_uint(Bs[k0 + t][n + g]);
                bf[ni][1] = __float_as_uint(Bs[k0 + t + 4][n + g]);
            }
#pragma unroll
            for (int mi = 0; mi < 2; mi++)
#pragma unroll
                for (int ni = 0; ni < 8; ni++)
                    mma8(acc[mi][ni], af[mi], bf[ni]);
        }
    }

    // epilogue: +b1, exact GELU, write hidden scratch
#pragma unroll
    for (int mi = 0; mi < 2; mi++) {
#pragma unroll
        for (int h2 = 0; h2 < 2; h2++) {
            int row = wm * 32 + mi * 16 + g + 8 * h2;
            int s = mt * BM + row;
            if (s < me) {
                float* hrow = g_h + ((size_t)e * NTOK + s) * HID;
#pragma unroll
                for (int ni = 0; ni < 8; ni++) {
                    int col = n0 + wn * 64 + ni * 8 + 2 * t;
                    float v0 = acc[mi][ni][2 * h2 + 0] + b1[e * HID + col];
                    float v1 = acc[mi][ni][2 * h2 + 1] + b1[e * HID + col + 1];
                    float2 o = make_float2(gelu_exact(v0), gelu_exact(v1));
                    *(float2*)(hrow + col) = o;
                }
            }
        }
    }
}

// ---------------- kernel 4: grouped GEMM2: out[tok] += c * (h @ w2) ----------------
__global__ __launch_bounds__(256) void ffn2_kernel(
    const float* __restrict__ w2, float* __restrict__ out)
{
    const int e  = blockIdx.z;
    const int me = g_cnt[e];
    const int mt = blockIdx.x;
    if (mt * BM >= me) return;
    const int n0 = blockIdx.y * BN;

    __shared__ float As[BK][PADM];
    __shared__ float Bs[BK][PADN];

    const int tid  = threadIdx.x;
    const int lane = tid & 31;
    const int wid  = tid >> 5;
    const int wm   = wid >> 1;
    const int wn   = wid & 1;
    const int g    = lane >> 2;
    const int t    = lane & 3;

    const int rA = tid >> 3;
    const int cA = (tid & 7) << 2;
    const float* aptr[4];
    bool aval[4];
#pragma unroll
    for (int i = 0; i < 4; i++) {
        int s = mt * BM + rA + 32 * i;
        aval[i] = (s < me);
        int srow = aval[i] ? s : 0;
        aptr[i] = g_h + ((size_t)e * NTOK + srow) * HID + cA;
    }
    const int kB = tid >> 5;
    const int cB = lane << 2;
    const float* bbase = w2 + (size_t)e * HID * DIM + n0 + cB;

    float4 pa[4], pb[4];
#pragma unroll
    for (int i = 0; i < 4; i++)
        pa[i] = aval[i] ? *(const float4*)(aptr[i]) : make_float4(0, 0, 0, 0);
#pragma unroll
    for (int i = 0; i < 4; i++)
        pb[i] = *(const float4*)(bbase + (size_t)(kB + 8 * i) * DIM);

    float acc[2][8][4];
#pragma unroll
    for (int a = 0; a < 2; a++)
#pragma unroll
        for (int b = 0; b < 8; b++)
#pragma unroll
            for (int q = 0; q < 4; q++) acc[a][b][q] = 0.f;

    const int KT = HID / BK;   // 128
    for (int kt = 0; kt < KT; kt++) {
        __syncthreads();
#pragma unroll
        for (int i = 0; i < 4; i++) {
            int r = rA + 32 * i;
            As[cA + 0][r] = __uint_as_float(f2tf(pa[i].x));
            As[cA + 1][r] = __uint_as_float(f2tf(pa[i].y));
            As[cA + 2][r] = __uint_as_float(f2tf(pa[i].z));
            As[cA + 3][r] = __uint_as_float(f2tf(pa[i].w));
            int kk = kB + 8 * i;
            Bs[kk][cB + 0] = __uint_as_float(f2tf(pb[i].x));
            Bs[kk][cB + 1] = __uint_as_float(f2tf(pb[i].y));
            Bs[kk][cB + 2] = __uint_as_float(f2tf(pb[i].z));
            Bs[kk][cB + 3] = __uint_as_float(f2tf(pb[i].w));
        }
        __syncthreads();
        if (kt + 1 < KT) {
            int ko = (kt + 1) * BK;
#pragma unroll
            for (int i = 0; i < 4; i++)
                pa[i] = aval[i] ? *(const float4*)(aptr[i] + ko) : make_float4(0, 0, 0, 0);
#pragma unroll
            for (int i = 0; i < 4; i++)
                pb[i] = *(const float4*)(bbase + (size_t)(ko + kB + 8 * i) * DIM);
        }
#pragma unroll
        for (int ks = 0; ks < 4; ks++) {
            const int k0 = ks * 8;
            uint32_t af[2][4];
#pragma unroll
            for (int mi = 0; mi < 2; mi++) {
                int m = wm * 32 + mi * 16;
                af[mi][0] = __float_as_uint(As[k0 + t][m + g]);
                af[mi][1] = __float_as_uint(As[k0 + t][m + g + 8]);
                af[mi][2] = __float_as_uint(As[k0 + t + 4][m + g]);
                af[mi][3] = __float_as_uint(As[k0 + t + 4][m + g + 8]);
            }
            uint32_t bf[8][2];
#pragma unroll
            for (int ni = 0; ni < 8; ni++) {
                int n = wn * 64 + ni * 8;
                bf[ni][0] = __float_as_uint(Bs[k0 + t][n + g]);
                bf[ni][1] = __float_as_uint(Bs[k0 + t + 4][n + g]);
            }
#pragma unroll
            for (int mi = 0; mi < 2; mi++)
#pragma unroll
                for (int ni = 0; ni < 8; ni++)
                    mma8(acc[mi][ni], af[mi], bf[ni]);
        }
    }

    // epilogue: scaled scatter-add into fused output
#pragma unroll
    for (int mi = 0; mi < 2; mi++) {
#pragma unroll
        for (int h2 = 0; h2 < 2; h2++) {
            int row = wm * 32 + mi * 16 + g + 8 * h2;
            int s = mt * BM + row;
            if (s < me) {
                int tok  = g_idx[e][s];
                float wc = g_wt[e][s];
                float* orow = out + (size_t)tok * DIM;
#pragma unroll
                for (int ni = 0; ni < 8; ni++) {
                    int col = n0 + wn * 64 + ni * 8 + 2 * t;
                    atomicAdd(orow + col,     wc * acc[mi][ni][2 * h2 + 0]);
                    atomicAdd(orow + col + 1, wc * acc[mi][ni][2 * h2 + 1]);
                }
            }
        }
    }
}

// ---------------- launch ----------------
extern "C" void kernel_launch(void* const* d_in, const int* in_sizes, int n_in,
                              void* d_out, int out_size)
{
    (void)in_sizes; (void)n_in; (void)out_size;
    const float* x  = (const float*)d_in[0];
    const float* ei = (const float*)d_in[1];
    const float* wg = (const float*)d_in[2];
    const float* bg = (const float*)d_in[3];
    const float* w1 = (const float*)d_in[4];
    const float* b1 = (const float*)d_in[5];
    const float* w2 = (const float*)d_in[6];
    const float* b2 = (const float*)d_in[7];
    float* out = (float*)d_out;

    gate_kernel<<<NTOK / 8, 256>>>(x, wg, bg, b2, out);
    compact_kernel<<<1, 256>>>();
    ffn1_kernel<<<dim3(NTOK / BM, HID / BN, NEXP), 256>>>(ei, w1, b1);
    ffn2_kernel<<<dim3(NTOK / BM, DIM / BN, NEXP), 256>>>(w2, out);
}

// round 3
// speedup vs baseline: 1.1632x; 1.1632x over previous
#include <cuda_runtime.h>
#include <cstdint>

#define NTOK 4096
#define DIM  1024
#define NEXP 8
#define HID  4096
#define THR  0.3f

#define BM 128
#define BN 128
#define BK 16

// ---------------- scratch (static device memory; no allocs anywhere) ----------------
__device__ float g_c[NTOK * NEXP];                 // combine weights per (token, expert)
__device__ int   g_idx[NEXP][NTOK];                // compacted token indices per expert
__device__ float g_wt[NEXP][NTOK];                 // compacted combine weights
__device__ int   g_cnt[NEXP];                      // tokens per expert
__device__ float g_h[(size_t)NEXP * NTOK * HID];   // hidden activations (tf32-rounded)

// ---------------- helpers ----------------
__device__ __forceinline__ uint32_t f2tf(float f) {
    uint32_t u;
    asm("cvt.rna.tf32.f32 %0, %1;" : "=r"(u) : "f"(f));
    return u;
}
__device__ __forceinline__ float rnatf(float f) { return __uint_as_float(f2tf(f)); }

__device__ __forceinline__ void mma8(float* c, const uint32_t* a, const uint32_t* b) {
    asm volatile(
        "mma.sync.aligned.m16n8k8.row.col.f32.tf32.tf32.f32 "
        "{%0,%1,%2,%3}, {%4,%5,%6,%7}, {%8,%9}, {%0,%1,%2,%3};"
        : "+f"(c[0]), "+f"(c[1]), "+f"(c[2]), "+f"(c[3])
        : "r"(a[0]), "r"(a[1]), "r"(a[2]), "r"(a[3]), "r"(b[0]), "r"(b[1]));
}

__device__ __forceinline__ float gelu_exact(float v) {
    return 0.5f * v * (1.0f + erff(v * 0.70710678118654752f));
}

// ---------------- kernel 1: gate scores, combine weights, out init with sum(c*b2) ----------------
__global__ __launch_bounds__(256) void gate_kernel(
    const float* __restrict__ x, const float* __restrict__ wg,
    const float* __restrict__ bg, const float* __restrict__ b2,
    float* __restrict__ out)
{
    __shared__ float wgs[DIM * 9];   // padded stride 9 -> conflict-free
    int tid = threadIdx.x;
    for (int i = tid; i < DIM * NEXP; i += 256)
        wgs[(i >> 3) * 9 + (i & 7)] = wg[i];
    __syncthreads();

    int lane = tid & 31, wid = tid >> 5;
    int n = blockIdx.x * 8 + wid;

    float s[NEXP];
#pragma unroll
    for (int e = 0; e < NEXP; e++) s[e] = 0.f;

    const float* xr = x + (size_t)n * DIM;
    for (int k = lane; k < DIM; k += 32) {
        float xv = xr[k];
#pragma unroll
        for (int e = 0; e < NEXP; e++) s[e] += xv * wgs[k * 9 + e];
    }
#pragma unroll
    for (int e = 0; e < NEXP; e++)
#pragma unroll
        for (int o = 16; o; o >>= 1)
            s[e] += __shfl_xor_sync(0xffffffffu, s[e], o);

    float mx = -1e30f;
#pragma unroll
    for (int e = 0; e < NEXP; e++) { s[e] += bg[e]; mx = fmaxf(mx, s[e]); }
    float sum = 0.f;
#pragma unroll
    for (int e = 0; e < NEXP; e++) { s[e] = expf(s[e] - mx); sum += s[e]; }
    float inv = 1.f / sum;
#pragma unroll
    for (int e = 0; e < NEXP; e++) s[e] *= inv;

    if (lane == 0) {
        float* gs = out + (size_t)NTOK * DIM + (size_t)n * NEXP;
#pragma unroll
        for (int e = 0; e < NEXP; e++) gs[e] = s[e];
    }

    float msum = 0.f; int cnt = 0;
#pragma unroll
    for (int e = 0; e < NEXP; e++) if (s[e] >= THR) { msum += s[e]; cnt++; }
    int top1 = 0; float best = s[0];
#pragma unroll
    for (int e = 1; e < NEXP; e++) if (s[e] > best) { best = s[e]; top1 = e; }
    float dn = 1.f / (msum + 1e-6f);
    float c[NEXP];
#pragma unroll
    for (int e = 0; e < NEXP; e++)
        c[e] = cnt ? ((s[e] >= THR) ? s[e] * dn : 0.f) : ((e == top1) ? 1.f : 0.f);

    if (lane == 0) {
#pragma unroll
        for (int e = 0; e < NEXP; e++) g_c[n * NEXP + e] = c[e];
    }

    for (int d = lane; d < DIM; d += 32) {
        float a = 0.f;
#pragma unroll
        for (int e = 0; e < NEXP; e++) a += c[e] * b2[e * DIM + d];
        out[(size_t)n * DIM + d] = a;
    }
}

// ---------------- kernel 2: deterministic per-expert compaction (1 warp per expert) ----------------
__global__ __launch_bounds__(256) void compact_kernel()
{
    int wid = threadIdx.x >> 5;
    int lane = threadIdx.x & 31;
    if (wid >= NEXP) return;
    int cnt = 0;
    for (int base = 0; base < NTOK; base += 32) {
        int n = base + lane;
        float c = g_c[n * NEXP + wid];
        unsigned m = __ballot_sync(0xffffffffu, c > 0.f);
        if (c > 0.f) {
            int pos = cnt + __popc(m & ((1u << lane) - 1u));
            g_idx[wid][pos] = n;
            g_wt[wid][pos]  = c;
        }
        cnt += __popc(m);
    }
    if (lane == 0) g_cnt[wid] = cnt;
}

// =====================================================================================
// FFN GEMMs: 4 warps/CTA, warp tile 64x64, CTA tile 128x128, BK=16.
//   As[k][m]  : stride 136 floats. STS conflict-free (thread==row), LDS frag conflict-free.
//   Bs[G][k][r]: G=n>>3, r=n&7, group stride 136 floats. STS.128 and LDS frag conflict-free.
// =====================================================================================

// ---------------- kernel 3: grouped GEMM1: h = gelu(gather(ei) @ w1 + b1), rna-rounded ----------------
__global__ __launch_bounds__(128, 2) void ffn1_kernel(
    const float* __restrict__ ei, const float* __restrict__ w1,
    const float* __restrict__ b1)
{
    __shared__ float As[BK * 136];
    __shared__ float Bs[16 * 136];

    const int e  = blockIdx.z;
    const int me = g_cnt[e];
    const int mt = blockIdx.x;
    if (mt * BM >= me) return;
    const int n0 = blockIdx.y * BN;

    const int tid  = threadIdx.x;
    const int lane = tid & 31;
    const int wid  = tid >> 5;
    const int wm   = wid >> 1;     // 0..1  (M halves of 64)
    const int wn   = wid & 1;      // 0..1  (N halves of 64)
    const int g    = lane >> 2;    // 0..7
    const int t    = lane & 3;     // 0..3

    // ---- A loader: one thread per row (gathered token) ----
    const int s0 = mt * BM + tid;
    const bool av = (s0 < me);
    const int tok = av ? g_idx[e][s0] : 0;
    const float* aptr = ei + ((size_t)e * NTOK + tok) * DIM;

    // ---- B loader: warp w loads rows 4w..4w+3; thread covers n-quad lane*4 ----
    const int bk4 = wid * 4;
    const float* bptr = w1 + (size_t)e * DIM * HID + n0 + lane * 4;
    float* bsts = Bs + (lane >> 1) * 136 + 4 * (lane & 1);

    float4 pa[4], pb[4];
#pragma unroll
    for (int q = 0; q < 4; q++)
        pa[q] = av ? *(const float4*)(aptr + 4 * q) : make_float4(0, 0, 0, 0);
#pragma unroll
    for (int i = 0; i < 4; i++)
        pb[i] = *(const float4*)(bptr + (size_t)(bk4 + i) * HID);

    float acc[4][8][4];
#pragma unroll
    for (int a = 0; a < 4; a++)
#pragma unroll
        for (int b = 0; b < 8; b++)
#pragma unroll
            for (int q = 0; q < 4; q++) acc[a][b][q] = 0.f;

    const int KT = DIM / BK;   // 64
    for (int kt = 0; kt < KT; kt++) {
        __syncthreads();
#pragma unroll
        for (int q = 0; q < 4; q++) {
            As[(4 * q + 0) * 136 + tid] = rnatf(pa[q].x);
            As[(4 * q + 1) * 136 + tid] = rnatf(pa[q].y);
            As[(4 * q + 2) * 136 + tid] = rnatf(pa[q].z);
            As[(4 * q + 3) * 136 + tid] = rnatf(pa[q].w);
        }
#pragma unroll
        for (int i = 0; i < 4; i++) {
            float4 v = make_float4(rnatf(pb[i].x), rnatf(pb[i].y),
                                   rnatf(pb[i].z), rnatf(pb[i].w));
            *(float4*)(bsts + (bk4 + i) * 8) = v;
        }
        __syncthreads();
        if (kt + 1 < KT) {
            const float* ap = aptr + (kt + 1) * BK;
#pragma unroll
            for (int q = 0; q < 4; q++)
                pa[q] = av ? *(const float4*)(ap + 4 * q) : make_float4(0, 0, 0, 0);
            const float* bp = bptr + (size_t)(kt + 1) * BK * HID;
#pragma unroll
            for (int i = 0; i < 4; i++)
                pb[i] = *(const float4*)(bp + (size_t)(bk4 + i) * HID);
        }
#pragma unroll
        for (int ks = 0; ks < 2; ks++) {
            const int k0 = ks * 8;
            uint32_t af[4][4];
#pragma unroll
            for (int mi = 0; mi < 4; mi++) {
                int m = wm * 64 + mi * 16;
                af[mi][0] = __float_as_uint(As[(k0 + t) * 136 + m + g]);
                af[mi][1] = __float_as_uint(As[(k0 + t) * 136 + m + g + 8]);
                af[mi][2] = __float_as_uint(As[(k0 + t + 4) * 136 + m + g]);
                af[mi][3] = __float_as_uint(As[(k0 + t + 4) * 136 + m + g + 8]);
            }
#pragma unroll
            for (int ni = 0; ni < 8; ni++) {
                int G = wn * 8 + ni;
                uint32_t bf[2];
                bf[0] = __float_as_uint(Bs[G * 136 + (k0 + t) * 8 + g]);
                bf[1] = __float_as_uint(Bs[G * 136 + (k0 + t + 4) * 8 + g]);
#pragma unroll
                for (int mi = 0; mi < 4; mi++)
                    mma8(acc[mi][ni], af[mi], bf);
            }
        }
    }

    // epilogue: +b1, exact GELU, rna-round, write hidden scratch
#pragma unroll
    for (int mi = 0; mi < 4; mi++) {
#pragma unroll
        for (int h2 = 0; h2 < 2; h2++) {
            int row = wm * 64 + mi * 16 + g + 8 * h2;
            int ss = mt * BM + row;
            if (ss < me) {
                float* hrow = g_h + ((size_t)e * NTOK + ss) * HID;
#pragma unroll
                for (int ni = 0; ni < 8; ni++) {
                    int col = n0 + wn * 64 + ni * 8 + 2 * t;
                    float v0 = acc[mi][ni][2 * h2 + 0] + b1[e * HID + col];
                    float v1 = acc[mi][ni][2 * h2 + 1] + b1[e * HID + col + 1];
                    float2 o = make_float2(rnatf(gelu_exact(v0)), rnatf(gelu_exact(v1)));
                    *(float2*)(hrow + col) = o;
                }
            }
        }
    }
}

// ---------------- kernel 4: grouped GEMM2: out[tok] += c * (h @ w2) ----------------
__global__ __launch_bounds__(128, 2) void ffn2_kernel(
    const float* __restrict__ w2, float* __restrict__ out)
{
    __shared__ float As[BK * 136];
    __shared__ float Bs[16 * 136];

    const int e  = blockIdx.z;
    const int me = g_cnt[e];
    const int mt = blockIdx.x;
    if (mt * BM >= me) return;
    const int n0 = blockIdx.y * BN;

    const int tid  = threadIdx.x;
    const int lane = tid & 31;
    const int wid  = tid >> 5;
    const int wm   = wid >> 1;
    const int wn   = wid & 1;
    const int g    = lane >> 2;
    const int t    = lane & 3;

    // A loader: one thread per compacted slot row of g_h (already tf32-rounded)
    const int s0 = mt * BM + tid;
    const float* aptr = g_h + ((size_t)e * NTOK + s0) * HID;   // rows >= me: stale, discarded

    const int bk4 = wid * 4;
    const float* bptr = w2 + (size_t)e * HID * DIM + n0 + lane * 4;
    float* bsts = Bs + (lane >> 1) * 136 + 4 * (lane & 1);

    float4 pa[4], pb[4];
#pragma unroll
    for (int q = 0; q < 4; q++) pa[q] = *(const float4*)(aptr + 4 * q);
#pragma unroll
    for (int i = 0; i < 4; i++) pb[i] = *(const float4*)(bptr + (size_t)(bk4 + i) * DIM);

    float acc[4][8][4];
#pragma unroll
    for (int a = 0; a < 4; a++)
#pragma unroll
        for (int b = 0; b < 8; b++)
#pragma unroll
            for (int q = 0; q < 4; q++) acc[a][b][q] = 0.f;

    const int KT = HID / BK;   // 256
    for (int kt = 0; kt < KT; kt++) {
        __syncthreads();
#pragma unroll
        for (int q = 0; q < 4; q++) {
            As[(4 * q + 0) * 136 + tid] = pa[q].x;
            As[(4 * q + 1) * 136 + tid] = pa[q].y;
            As[(4 * q + 2) * 136 + tid] = pa[q].z;
            As[(4 * q + 3) * 136 + tid] = pa[q].w;
        }
#pragma unroll
        for (int i = 0; i < 4; i++) {
            float4 v = make_float4(rnatf(pb[i].x), rnatf(pb[i].y),
                                   rnatf(pb[i].z), rnatf(pb[i].w));
            *(float4*)(bsts + (bk4 + i) * 8) = v;
        }
        __syncthreads();
        if (kt + 1 < KT) {
            const float* ap = aptr + (kt + 1) * BK;
#pragma unroll
            for (int q = 0; q < 4; q++) pa[q] = *(const float4*)(ap + 4 * q);
            const float* bp = bptr + (size_t)(kt + 1) * BK * DIM;
#pragma unroll
            for (int i = 0; i < 4; i++) pb[i] = *(const float4*)(bp + (size_t)(bk4 + i) * DIM);
        }
#pragma unroll
        for (int ks = 0; ks < 2; ks++) {
            const int k0 = ks * 8;
            uint32_t af[4][4];
#pragma unroll
            for (int mi = 0; mi < 4; mi++) {
                int m = wm * 64 + mi * 16;
                af[mi][0] = __float_as_uint(As[(k0 + t) * 136 + m + g]);
                af[mi][1] = __float_as_uint(As[(k0 + t) * 136 + m + g + 8]);
                af[mi][2] = __float_as_uint(As[(k0 + t + 4) * 136 + m + g]);
                af[mi][3] = __float_as_uint(As[(k0 + t + 4) * 136 + m + g + 8]);
            }
#pragma unroll
            for (int ni = 0; ni < 8; ni++) {
                int G = wn * 8 + ni;
                uint32_t bf[2];
                bf[0] = __float_as_uint(Bs[G * 136 + (k0 + t) * 8 + g]);
                bf[1] = __float_as_uint(Bs[G * 136 + (k0 + t + 4) * 8 + g]);
#pragma unroll
                for (int mi = 0; mi < 4; mi++)
                    mma8(acc[mi][ni], af[mi], bf);
            }
        }
    }

    // epilogue: scaled scatter-add into fused output
#pragma unroll
    for (int mi = 0; mi < 4; mi++) {
#pragma unroll
        for (int h2 = 0; h2 < 2; h2++) {
            int row = wm * 64 + mi * 16 + g + 8 * h2;
            int ss = mt * BM + row;
            if (ss < me) {
                int tok  = g_idx[e][ss];
                float wc = g_wt[e][ss];
                float* orow = out + (size_t)tok * DIM;
#pragma unroll
                for (int ni = 0; ni < 8; ni++) {
                    int col = n0 + wn * 64 + ni * 8 + 2 * t;
                    atomicAdd(orow + col,     wc * acc[mi][ni][2 * h2 + 0]);
                    atomicAdd(orow + col + 1, wc * acc[mi][ni][2 * h2 + 1]);
                }
            }
        }
    }
}

// ---------------- launch ----------------
extern "C" void kernel_launch(void* const* d_in, const int* in_sizes, int n_in,
                              void* d_out, int out_size)
{
    (void)in_sizes; (void)n_in; (void)out_size;
    const float* x  = (const float*)d_in[0];
    const float* ei = (const float*)d_in[1];
    const float* wg = (const float*)d_in[2];
    const float* bg = (const float*)d_in[3];
    const float* w1 = (const float*)d_in[4];
    const float* b1 = (const float*)d_in[5];
    const float* w2 = (const float*)d_in[6];
    const float* b2 = (const float*)d_in[7];
    float* out = (float*)d_out;

    gate_kernel<<<NTOK / 8, 256>>>(x, wg, bg, b2, out);
    compact_kernel<<<1, 256>>>();
    ffn1_kernel<<<dim3(NTOK / BM, HID / BN, NEXP), 128>>>(ei, w1, b1);
    ffn2_kernel<<<dim3(NTOK / BM, DIM / BN, NEXP), 128>>>(w2, out);
}